// round 14
// baseline (speedup 1.0000x reference)
#include <cuda_runtime.h>
#include <cuda_bf16.h>
#include <math.h>
#include <stdint.h>

// Problem constants
#define B 64
#define S 512
#define E 768
#define H 64
#define G 192   // 3H
#define T 16
#define P 32

// quantization scales
#define QSA (127.0f / 6.0f)
#define QSW (127.0f / 0.6f)
#define QINV (1.0f / (QSA * QSW))

// ---------------- scratch ----------------
__device__ float g_xp_f[B * S * G];
__device__ float g_xp_b[B * S * G];
__device__ float g_lstm[B * S * 2 * H];
__device__ float g_qkv[B * S * 3 * P];
__device__ float g_av[B * S * P];
__device__ float g_emis[B * S * T];
__device__ float g_weff1T[T * 2 * H];
__device__ float g_weff2T[T * P];
__device__ float g_beff[T];
__device__ float g_nll[B];
__device__ int   g_flags[256 * 6];     // xp tiles (m_tile, n_tile of 64)
__device__ int   g_done[2 * B];
__device__ int   g_edone[2 * B];
__device__ int   g_acount[B];
__device__ int8_t g_bert_q[B * S * E];
__device__ int8_t g_wq[2 * G * E];

__device__ __forceinline__ float sigmoidf_(float x) { return 1.0f / (1.0f + __expf(-x)); }
__device__ __forceinline__ float tanh_fast(float x) {
    float y; asm("tanh.approx.f32 %0, %1;" : "=f"(y) : "f"(x)); return y;
}
__device__ __forceinline__ void cp16(uint32_t s, const void* g) {
    asm volatile("cp.async.cg.shared.global [%0], [%1], 16;\n" :: "r"(s), "l"(g));
}
__device__ __forceinline__ void cp_commit() { asm volatile("cp.async.commit_group;\n"); }
template <int N> __device__ __forceinline__ void cp_wait() {
    asm volatile("cp.async.wait_group %0;\n" :: "n"(N));
}
__device__ __forceinline__ int q8v(float x, float s) {
    float v = fminf(fmaxf(x * s, -127.f), 127.f);
    return __float2int_rn(v);
}
__device__ __forceinline__ uint2 quant8(float4 v0, float4 v1, float s) {
    uint2 o;
    o.x = (uint32_t)(q8v(v0.x, s) & 255) | ((uint32_t)(q8v(v0.y, s) & 255) << 8)
        | ((uint32_t)(q8v(v0.z, s) & 255) << 16) | ((uint32_t)(q8v(v0.w, s) & 255) << 24);
    o.y = (uint32_t)(q8v(v1.x, s) & 255) | ((uint32_t)(q8v(v1.y, s) & 255) << 8)
        | ((uint32_t)(q8v(v1.z, s) & 255) << 16) | ((uint32_t)(q8v(v1.w, s) & 255) << 24);
    return o;
}

// =================================================================
// MEGA: GRU+emis+CRF (0..127) + GEMM (128..1663, BN=64) + attn (1664..2175)
// 3 blocks/SM target: regs<=85, DSM 46080
// =================================================================
#define RSTR 20                         // u32 per smem row (64B + 16B pad)
#define STAGE_UQ (192 * RSTR)           // 3840 u32 (128 A rows + 64 B rows)
#define NSTAGE 3
#define DSM_BYTES (NSTAGE * STAGE_UQ * 4)   // 46080
#define KCQ 64
#define NITER (E / KCQ)                 // 12
#define GRU_BLOCKS 128
#define GEMM_BLOCKS 1536                // 256 m_tiles x 6 n_tiles(64)
#define ATTN_OFF (GRU_BLOCKS + GEMM_BLOCKS)
#define TOTAL_BLOCKS (ATTN_OFF + 512)

__device__ __forceinline__ void poll3(int i0, int tid) {
    if (tid == 0) {
        volatile int* f = g_flags;
        while (f[i0] == 0) __nanosleep(64);
        while (f[i0 + 1] == 0) __nanosleep(64);
        while (f[i0 + 2] == 0) __nanosleep(64);
        __threadfence();
    }
    __syncthreads();
}

__global__ void __launch_bounds__(256, 3) mega_kernel(
    const float* __restrict__ bf, const float* __restrict__ bb,
    const float* __restrict__ Whh_f, const float* __restrict__ Whh_b,
    const float* __restrict__ bhh_f, const float* __restrict__ bhh_b,
    const int* __restrict__ targets, const float* __restrict__ crf_start,
    const float* __restrict__ crf_end, const float* __restrict__ crf_trans)
{
    extern __shared__ __align__(16) float dsm[];
    const int tid = threadIdx.x;

    if (blockIdx.x < GRU_BLOCKS) {
        // ---------------- GRU (consumer), weights 32 reg + 32 smem ----------------
        const int b = blockIdx.x >> 1;
        const int dir = blockIdx.x & 1;
        float* hsh = dsm;               // 64
        float* ghsh = dsm + 64;         // 192
        float* wsm = dsm + 256;         // [32][192]
        const bool act = (tid < G);
        const float* Whh = dir ? Whh_b : Whh_f;

        float wreg[32];
        float bias = 0.f;
        if (act) {
            const float4* wr = (const float4*)(Whh + (size_t)tid * H);
#pragma unroll
            for (int i = 0; i < 8; i++) {
                float4 v = __ldg(wr + i);
                wreg[4 * i] = v.x; wreg[4 * i + 1] = v.y;
                wreg[4 * i + 2] = v.z; wreg[4 * i + 3] = v.w;
            }
            bias = (dir ? bhh_b : bhh_f)[tid];
        }
        // cooperative fill of wsm[k2][g] = Whh[g][32+k2]
        for (int i = tid; i < 32 * G; i += 256) {
            int k2 = i / G, g = i % G;
            wsm[k2 * G + g] = __ldg(Whh + (size_t)g * H + 32 + k2);
        }
        if (tid < H) hsh[tid] = 0.f;

        const int te0 = dir ? (S - 1) : 0;
        {
            int c0 = te0 >> 7;
            poll3((b * 4 + c0) * 6 + dir * 3, tid);
        }

        const float* xp = (dir ? g_xp_b : g_xp_f) + (size_t)b * S * G;
        float xr = 0.f, xz = 0.f, xn = 0.f;
        if (tid < H) {
            const float* xrow = xp + (size_t)te0 * G;
            xr = xrow[tid]; xz = xrow[H + tid]; xn = xrow[2 * H + tid];
        }
        for (int t = 0; t < S; t++) {
            const int te = dir ? (S - 1 - t) : t;
            if (act) {
                float a0 = bias, a1 = 0.f, a2 = 0.f, a3 = 0.f;
                const float4* hv = (const float4*)hsh;
#pragma unroll
                for (int i = 0; i < 8; i++) {
                    float4 h4 = hv[i];
                    a0 = fmaf(wreg[4 * i], h4.x, a0);
                    a1 = fmaf(wreg[4 * i + 1], h4.y, a1);
                    a2 = fmaf(wreg[4 * i + 2], h4.z, a2);
                    a3 = fmaf(wreg[4 * i + 3], h4.w, a3);
                }
#pragma unroll 8
                for (int k = 0; k < 32; k += 2) {
                    a0 = fmaf(wsm[k * G + tid], hsh[32 + k], a0);
                    a1 = fmaf(wsm[(k + 1) * G + tid], hsh[33 + k], a1);
                }
                ghsh[tid] = (a0 + a1) + (a2 + a3);
            }
            __syncthreads();
            if (((t + 1) & 127) == 0 && (t + 1) < S) {
                int ten = dir ? (S - 2 - t) : (t + 1);
                poll3((b * 4 + (ten >> 7)) * 6 + dir * 3, tid);
            }
            float nxr = 0.f, nxz = 0.f, nxn = 0.f;
            if (t < S - 1 && tid < H) {
                const float* xrow = xp + (size_t)(dir ? (S - 2 - t) : (t + 1)) * G;
                nxr = xrow[tid]; nxz = xrow[H + tid]; nxn = xrow[2 * H + tid];
            }
            if (tid < H) {
                float r = sigmoidf_(xr + ghsh[tid]);
                float z = sigmoidf_(xz + ghsh[H + tid]);
                float nw = tanh_fast(xn + r * ghsh[2 * H + tid]);
                float hn = (1.f - z) * nw + z * hsh[tid];
                hsh[tid] = hn;
                g_lstm[((size_t)b * S + te) * (2 * H) + dir * H + tid] = hn;
            }
            __syncthreads();
            xr = nxr; xz = nxz; xn = nxn;
        }

        // ---- handshake ----
        if (tid == 0) {
            __threadfence();
            atomicExch(&g_done[2 * b + dir], 1);
            volatile int* dn = g_done;
            while (dn[2 * b + (1 - dir)] == 0) __nanosleep(64);
            volatile int* ac = g_acount;
            while (ac[b] != 8) __nanosleep(64);
            __threadfence();
        }
        __syncthreads();

        // ---- emissions for rows [dir*256, dir*256+256) of batch b ----
        float* lrow = dsm;
        float* arow = dsm + 2048;
        float* w1s  = dsm + 2560;
        float* w2s  = dsm + 4688;
        float* bes  = dsm + 5280;
        for (int i = tid; i < T * 2 * H; i += 256) {
            int t = i >> 7, j = i & 127;
            w1s[t * 133 + j] = g_weff1T[i];
        }
        for (int i = tid; i < T * P; i += 256) {
            int t = i >> 5, d = i & 31;
            w2s[t * 37 + d] = g_weff2T[i];
        }
        if (tid < T) bes[tid] = g_beff[tid];
        __syncthreads();

        const int rbase = b * S + dir * 256;
        for (int ch = 0; ch < 16; ch++) {
            const int r0 = rbase + ch * 16;
            for (int i = tid; i < 16 * 2 * H; i += 256) lrow[i] = g_lstm[(size_t)r0 * 2 * H + i];
            for (int i = tid; i < 16 * P; i += 256) arow[i] = g_av[(size_t)r0 * P + i];
            __syncthreads();
            const int rr = tid >> 4;
            const int t = tid & 15;
            float acc = bes[t];
            const float* lr = lrow + rr * 2 * H;
            const float* w1 = w1s + t * 133;
#pragma unroll
            for (int i = 0; i < 2 * H; i += 4) {
                acc = fmaf(lr[i], w1[i], acc);
                acc = fmaf(lr[i + 1], w1[i + 1], acc);
                acc = fmaf(lr[i + 2], w1[i + 2], acc);
                acc = fmaf(lr[i + 3], w1[i + 3], acc);
            }
            const float* ar = arow + rr * P;
            const float* w2 = w2s + t * 37;
#pragma unroll
            for (int i = 0; i < P; i += 4) {
                acc = fmaf(ar[i], w2[i], acc);
                acc = fmaf(ar[i + 1], w2[i + 1], acc);
                acc = fmaf(ar[i + 2], w2[i + 2], acc);
                acc = fmaf(ar[i + 3], w2[i + 3], acc);
            }
            g_emis[(size_t)(r0 + rr) * T + t] = acc;
            __syncthreads();
        }

        if (tid == 0) {
            __threadfence();
            atomicExch(&g_edone[2 * b + dir], 1);
        }
        if (dir == 1) return;

        // ---- CRF for batch b ----
        if (tid == 0) {
            volatile int* ed = g_edone;
            while (ed[2 * b + 1] == 0) __nanosleep(64);
            __threadfence();
        }
        __syncthreads();

        float* tr      = dsm;
        float* alpha_s = dsm + 272;
        float* beta_s  = dsm + 288;
        float* numw    = dsm + 304;
        for (int i = tid; i < T * T; i += 256) tr[(i >> 4) * 17 + (i & 15)] = crf_trans[i];
        __syncthreads();

        const int wid = tid >> 5, lane = tid & 31;
        const int j = lane & 15, half = lane >> 4;
        const int* tg = targets + (size_t)b * S;
        const float* em_b = g_emis + (size_t)b * S * T;
        const int src_base = half * 24;

        if (wid < 2) {
            float num = 0.f;
            for (int t = tid; t < S; t += 64) {
                int cur = tg[t];
                num += em_b[t * T + cur];
                if (t < S - 1) num += tr[cur * 17 + tg[t + 1]];
            }
#pragma unroll
            for (int o = 16; o > 0; o >>= 1) num += __shfl_xor_sync(0xffffffffu, num, o);
            if (lane == 0) numw[wid] = num;

            if (wid == 0) {
                float Ereg[8];
#pragma unroll
                for (int k = 0; k < 8; k++) Ereg[k] = __expf(tr[(half * 8 + k) * 17 + j]);
                float a = crf_start[j] + em_b[j];
                float em = em_b[T + j];
                for (int t = 1; t <= 255; t++) {
                    float em_next = em_b[(t + 1) * T + j];
                    float anchor = __shfl_sync(0xffffffffu, a, 0);
                    float e = __expf(a - anchor);
                    float acc0 = 0.f, acc1 = 0.f;
#pragma unroll
                    for (int i = 0; i < 8; i += 2) {
                        float e0 = __shfl_sync(0xffffffffu, e, src_base + i);
                        float e1 = __shfl_sync(0xffffffffu, e, src_base + i + 1);
                        acc0 = fmaf(e0, Ereg[i], acc0);
                        acc1 = fmaf(e1, Ereg[i + 1], acc1);
                    }
                    float acc = acc0 + acc1;
                    acc += __shfl_xor_sync(0xffffffffu, acc, 16);
                    a = anchor + __logf(acc) + em;
                    em = em_next;
                }
                if (half == 0) alpha_s[j] = a;
            } else {
                float EregB[8];
#pragma unroll
                for (int i2 = 0; i2 < 8; i2++) EregB[i2] = __expf(tr[j * 17 + half * 8 + i2]);
                float bt = crf_end[j];
                float em1 = em_b[511 * T + j];
                for (int t = 510; t >= 255; t--) {
                    float em_next = (t > 255) ? em_b[t * T + j] : 0.f;
                    float g = bt + em1;
                    float anchor = __shfl_sync(0xffffffffu, g, 0);
                    float e = __expf(g - anchor);
                    float acc0 = 0.f, acc1 = 0.f;
#pragma unroll
                    for (int i2 = 0; i2 < 8; i2 += 2) {
                        float e0 = __shfl_sync(0xffffffffu, e, src_base + i2);
                        float e1 = __shfl_sync(0xffffffffu, e, src_base + i2 + 1);
                        acc0 = fmaf(e0, EregB[i2], acc0);
                        acc1 = fmaf(e1, EregB[i2 + 1], acc1);
                    }
                    float acc = acc0 + acc1;
                    acc += __shfl_xor_sync(0xffffffffu, acc, 16);
                    bt = anchor + __logf(acc);
                    em1 = em_next;
                }
                if (half == 0) beta_s[j] = bt;
            }
        }
        __syncthreads();

        if (wid == 0) {
            float v = (lane < T) ? (alpha_s[lane] + beta_s[lane]) : -1e30f;
            float m = v;
#pragma unroll
            for (int o = 16; o > 0; o >>= 1) m = fmaxf(m, __shfl_xor_sync(0xffffffffu, m, o));
            float e = (lane < T) ? __expf(v - m) : 0.f;
#pragma unroll
            for (int o = 16; o > 0; o >>= 1) e += __shfl_xor_sync(0xffffffffu, e, o);
            if (lane == 0) {
                float s_num = numw[0] + numw[1] + crf_start[tg[0]] + crf_end[tg[S - 1]];
                g_nll[b] = (m + __logf(e)) - s_num;
            }
        }
    } else if (blockIdx.x < ATTN_OFF) {
        // ---------------- dual-pipe int8 GEMM, BN=64 ----------------
        const int bid = blockIdx.x - GRU_BLOCKS;
        const int nidx = bid % 6;
        const int r = bid / 6;            // 0..255
        const int p = r >> 7;
        const int q = r & 127;
        const int batch = q & 63;
        const int which = q >> 6;
        const int chunk = which ? (3 - p) : p;
        const int m_tile = batch * 4 + chunk;
        const int bm = m_tile * 128;
        const int bn = nidx * 64;

        const int wid = tid >> 5, lane = tid & 31;
        const uint32_t smb = (uint32_t)__cvta_generic_to_shared(dsm);

        // loaders: A 512 tasks (2/thread), B 256 tasks (1/thread)
        int ar0 = (tid) >> 2, ac0 = tid & 3;
        int ar1 = (tid + 256) >> 2, ac1 = (tid + 256) & 3;
        int br = tid >> 2, bc = tid & 3;
        const int8_t* ap0 = g_bert_q + (size_t)(bm + ar0) * E + ac0 * 16;
        const int8_t* ap1 = g_bert_q + (size_t)(bm + ar1) * E + ac1 * 16;
        const int8_t* bp0 = g_wq + (size_t)(bn + br) * E + bc * 16;

        // prologue: stages 0,1
#pragma unroll
        for (int s = 0; s < 2; s++) {
            uint32_t sb = smb + s * STAGE_UQ * 4;
            cp16(sb + (ar0 * RSTR + ac0 * 4) * 4, ap0 + s * KCQ);
            cp16(sb + (ar1 * RSTR + ac1 * 4) * 4, ap1 + s * KCQ);
            cp16(sb + ((128 + br) * RSTR + bc * 4) * 4, bp0 + s * KCQ);
            cp_commit();
        }

        if (wid < 4) {
            // tensor pipe: rows bm + wid*16 .. +15, cols bn..bn+63
            const int grp = lane >> 2, tig = lane & 3;
            const int wm = wid * 16;
            int acc[8][4];
#pragma unroll
            for (int nt = 0; nt < 8; nt++)
#pragma unroll
                for (int d = 0; d < 4; d++) acc[nt][d] = 0;

            for (int c = 0; c < NITER; c++) {
                if (c < 11) cp_wait<1>(); else cp_wait<0>();
                __syncthreads();
                if (c + 2 < NITER) {
                    const int st = (c + 2) % NSTAGE;
                    const int kn = (c + 2) * KCQ;
                    uint32_t sb = smb + st * STAGE_UQ * 4;
                    cp16(sb + (ar0 * RSTR + ac0 * 4) * 4, ap0 + kn);
                    cp16(sb + (ar1 * RSTR + ac1 * 4) * 4, ap1 + kn);
                    cp16(sb + ((128 + br) * RSTR + bc * 4) * 4, bp0 + kn);
                    cp_commit();
                }
                const int s = c % NSTAGE;
                const uint32_t* As = (const uint32_t*)dsm + s * STAGE_UQ;
                const uint32_t* Bs = As + 128 * RSTR;
#pragma unroll
                for (int ks = 0; ks < 2; ks++) {
                    const int ko = ks * 8;
                    uint32_t afr[4];
                    const uint32_t* pa = As + (wm + grp) * RSTR + ko + tig;
                    afr[0] = pa[0];
                    afr[1] = pa[8 * RSTR];
                    afr[2] = pa[4];
                    afr[3] = pa[8 * RSTR + 4];
#pragma unroll
                    for (int nt = 0; nt < 8; nt++) {
                        const uint32_t* pb = Bs + (nt * 8 + grp) * RSTR + ko + tig;
                        uint32_t b0 = pb[0], b1 = pb[4];
                        asm volatile(
                            "mma.sync.aligned.m16n8k32.row.col.s32.s8.s8.s32 "
                            "{%0,%1,%2,%3},{%4,%5,%6,%7},{%8,%9},{%0,%1,%2,%3};"
                            : "+r"(acc[nt][0]), "+r"(acc[nt][1]),
                              "+r"(acc[nt][2]), "+r"(acc[nt][3])
                            : "r"(afr[0]), "r"(afr[1]), "r"(afr[2]), "r"(afr[3]),
                              "r"(b0), "r"(b1));
                    }
                }
            }
            int m0 = bm + wm + grp;
#pragma unroll
            for (int nt = 0; nt < 8; nt++) {
                int n = bn + nt * 8 + 2 * tig;
                float* dst; const float* bp; int nn;
                if (n < G) { dst = g_xp_f; bp = bf; nn = n; }
                else       { dst = g_xp_b; bp = bb; nn = n - G; }
                float b0 = __ldg(bp + nn), b1 = __ldg(bp + nn + 1);
                *(float2*)(dst + (size_t)m0 * G + nn) =
                    make_float2((float)acc[nt][0] * QINV + b0, (float)acc[nt][1] * QINV + b1);
                *(float2*)(dst + (size_t)(m0 + 8) * G + nn) =
                    make_float2((float)acc[nt][2] * QINV + b0, (float)acc[nt][3] * QINV + b1);
            }
        } else {
            // fma pipe: dp4a, rows bm+64..bm+127, cols bn..bn+63
            const int local = tid - 128;
            const int tx = local & 15;        // cols tx + 16j (j<4)
            const int ty = local >> 4;        // rows 64 + ty + 8i (i<8)
            int acc[8][4];
#pragma unroll
            for (int i = 0; i < 8; i++)
#pragma unroll
                for (int j = 0; j < 4; j++) acc[i][j] = 0;

            for (int c = 0; c < NITER; c++) {
                if (c < 11) cp_wait<1>(); else cp_wait<0>();
                __syncthreads();
                if (c + 2 < NITER) {
                    const int st = (c + 2) % NSTAGE;
                    const int kn = (c + 2) * KCQ;
                    uint32_t sb = smb + st * STAGE_UQ * 4;
                    cp16(sb + (ar0 * RSTR + ac0 * 4) * 4, ap0 + kn);
                    cp16(sb + (ar1 * RSTR + ac1 * 4) * 4, ap1 + kn);
                    cp16(sb + ((128 + br) * RSTR + bc * 4) * 4, bp0 + kn);
                    cp_commit();
                }
                const int s = c % NSTAGE;
                const uint32_t* As = (const uint32_t*)dsm + s * STAGE_UQ;
                const uint32_t* Bs = As + 128 * RSTR;
#pragma unroll
                for (int k4 = 0; k4 < 16; k4++) {
                    uint32_t av[8], bv[4];
#pragma unroll
                    for (int i = 0; i < 8; i++) av[i] = As[(64 + ty + 8 * i) * RSTR + k4];
#pragma unroll
                    for (int j = 0; j < 4; j++) bv[j] = Bs[(tx + 16 * j) * RSTR + k4];
#pragma unroll
                    for (int i = 0; i < 8; i++)
#pragma unroll
                        for (int j = 0; j < 4; j++)
                            acc[i][j] = __dp4a((int)av[i], (int)bv[j], acc[i][j]);
                }
            }
#pragma unroll
            for (int j = 0; j < 4; j++) {
                int n = bn + tx + 16 * j;
                float* dst; const float* bp; int nn;
                if (n < G) { dst = g_xp_f; bp = bf; nn = n; }
                else       { dst = g_xp_b; bp = bb; nn = n - G; }
                float bj = __ldg(bp + nn);
#pragma unroll
                for (int i = 0; i < 8; i++) {
                    int m0 = bm + 64 + ty + 8 * i;
                    dst[(size_t)m0 * G + nn] = (float)acc[i][j] * QINV + bj;
                }
            }
        }
        __syncthreads();
        if (tid == 0) {
            __threadfence();
            atomicExch(&g_flags[m_tile * 6 + nidx], 1);
        }
    } else {
        // ---------------- flash attention ----------------
        const int bid = blockIdx.x - ATTN_OFF;
        const int qt = bid & 7, b = bid >> 3;
        float* Ks = dsm;
        float* Vs = dsm + 64 * 36;
        float* psh = dsm + 2 * 64 * 36;
        const int q = tid >> 2, kg = tid & 3;
        const int qg = qt * 64 + q;
        const float scale = 0.17677669529663689f;

        float4 qv[8];
        {
            const float4* qp = (const float4*)(g_qkv + ((size_t)b * S + qg) * (3 * P));
#pragma unroll
            for (int i = 0; i < 8; i++) qv[i] = __ldg(qp + i);
        }
        float av0[4] = {0.f, 0.f, 0.f, 0.f}, av1[4] = {0.f, 0.f, 0.f, 0.f};
        float mrun = -1e30f, lrun = 0.f;

        for (int kt = 0; kt < 8; kt++) {
            __syncthreads();
            for (int i = tid; i < 64 * P; i += 256) {
                int row = i >> 5, d = i & 31;
                const float* base = g_qkv + ((size_t)b * S + kt * 64 + row) * (3 * P);
                Ks[row * 36 + d] = base[P + d];
                Vs[row * 36 + d] = base[2 * P + d];
            }
            __syncthreads();

            float sv[16];
            float tmax = -1e30f;
#pragma unroll
            for (int kl = 0; kl < 16; kl++) {
                int k = kg + kl * 4;
                const float4* kr = (const float4*)(Ks + k * 36);
                float d0 = 0.f, d1 = 0.f, d2 = 0.f, d3 = 0.f;
#pragma unroll
                for (int i = 0; i < 8; i += 4) {
                    float4 k0 = kr[i], k1 = kr[i + 1], k2 = kr[i + 2], k3 = kr[i + 3];
                    d0 = fmaf(qv[i].x, k0.x, d0); d0 = fmaf(qv[i].y, k0.y, d0);
                    d0 = fmaf(qv[i].z, k0.z, d0); d0 = fmaf(qv[i].w, k0.w, d0);
                    d1 = fmaf(qv[i+1].x, k1.x, d1); d1 = fmaf(qv[i+1].y, k1.y, d1);
                    d1 = fmaf(qv[i+1].z, k1.z, d1); d1 = fmaf(qv[i+1].w, k1.w, d1);
                    d2 = fmaf(qv[i+2].x, k2.x, d2); d2 = fmaf(qv[i+2].y, k2.y, d2);
                    d2 = fmaf(qv[i+2].z, k2.z, d2); d2 = fmaf(qv[i+2].w, k2.w, d2);
                    d3 = fmaf(qv[i+3].x, k3.x, d3); d3 = fmaf(qv[i+3].y, k3.y, d3);
                    d3 = fmaf(qv[i+3].z, k3.z, d3); d3 = fmaf(qv[i+3].w, k3.w, d3);
                }
                sv[kl] = ((d0 + d1) + (d2 + d3)) * scale;
                tmax = fmaxf(tmax, sv[kl]);
            }
            tmax = fmaxf(tmax, __shfl_xor_sync(0xffffffffu, tmax, 1));
            tmax = fmaxf(tmax, __shfl_xor_sync(0xffffffffu, tmax, 2));
            float mnew = fmaxf(mrun, tmax);
            float corr = __expf(mrun - mnew);
            float tsum = 0.f;
#pragma unroll
            for (int kl = 0; kl < 16; kl++) {
                float e = __expf(sv[kl] - mnew);
                psh[q * 68 + kg + kl * 4] = e;
                tsum += e;
            }
            tsum += __shfl_xor_sync(0xffffffffu, tsum, 1);
            tsum += __shfl_xor_sync(0xffffffffu, tsum, 2);
            lrun = lrun * corr + tsum;
            mrun = mnew;
#pragma unroll
            for (int j = 0; j < 4; j++) { av0[j] *= corr; av1[j] *= corr; }
            __syncwarp();
#pragma unroll 4
            for (int k = 0; k < 64; k++) {
                float pv = psh[q * 68 + k];
                const float4* vr = (const float4*)(Vs + k * 36 + kg * 8);
                float4 v0 = vr[0], v1 = vr[1];
                av0[0] = fmaf(pv, v0.x, av0[0]); av0[1] = fmaf(pv, v0.y, av0[1]);
                av0[2] = fmaf(pv, v0.z, av0[2]); av0[3] = fmaf(pv, v0.w, av0[3]);
                av1[0] = fmaf(pv, v1.x, av1[0]); av1[1] = fmaf(pv, v1.y, av1[1]);
                av1[2] = fmaf(pv, v1.z, av1[2]); av1[3] = fmaf(pv, v1.w, av1[3]);
            }
            __syncwarp();
        }
        float inv = 1.0f / lrun;
        float* op = g_av + ((size_t)b * S + qg) * P + kg * 8;
        *(float4*)(op) = make_float4(av0[0] * inv, av0[1] * inv, av0[2] * inv, av0[3] * inv);
        *(float4*)(op + 4) = make_float4(av1[0] * inv, av1[1] * inv, av1[2] * inv, av1[3] * inv);
        __syncthreads();
        if (tid == 0) {
            __threadfence();
            atomicAdd(&g_acount[b], 1);
        }
    }
}

// =================================================================
// PREP: bert->int8 + qkv + Wih->int8 + weff/flags (R12 form)
// =================================================================
#define CVT_BLOCKS 12288
#define QKV_BLOCKS 12288
#define WCVT_BLOCKS 144
__global__ void prep_kernel(const float* __restrict__ bert,
                            const float* __restrict__ in2, const float* __restrict__ W,
                            const float* __restrict__ bias,
                            const float* __restrict__ Wf, const float* __restrict__ Wb,
                            const float* __restrict__ Wdense, const float* __restrict__ opw,
                            const float* __restrict__ opb, const float* __restrict__ Wfuse) {
    const int bx = blockIdx.x;
    if (bx < CVT_BLOCKS) {
        int base = bx * 2048 + threadIdx.x * 8;
        float4 v0 = *(const float4*)(bert + base);
        float4 v1 = *(const float4*)(bert + base + 4);
        *(uint2*)(g_bert_q + base) = quant8(v0, v1, QSA);
    } else if (bx < CVT_BLOCKS + QKV_BLOCKS) {
        int idx = (bx - CVT_BLOCKS) * 256 + threadIdx.x;
        int m = idx / (3 * P);
        int n = idx % (3 * P);
        const float4* x = (const float4*)(in2 + (size_t)m * P);
        const float4* wv = (const float4*)(W + (size_t)n * P);
        float acc = bias[n];
#pragma unroll
        for (int k = 0; k < 8; k++) {
            float4 a = __ldg(x + k), b = __ldg(wv + k);
            acc = fmaf(a.x, b.x, acc); acc = fmaf(a.y, b.y, acc);
            acc = fmaf(a.z, b.z, acc); acc = fmaf(a.w, b.w, acc);
        }
        g_qkv[idx] = acc;
    } else if (bx < CVT_BLOCKS + QKV_BLOCKS + WCVT_BLOCKS) {
        int base = (bx - CVT_BLOCKS - QKV_BLOCKS) * 2048 + threadIdx.x * 8;
        const int half = G * E;
        const float* src = (base < half) ? (Wf + base) : (Wb + base - half);
        float4 v0 = *(const float4*)(src);
        float4 v1 = *(const float4*)(src + 4);
        *(uint2*)(g_wq + base) = quant8(v0, v1, QSW);
    } else {
        int tid = threadIdx.x;
        for (int i = tid; i < 256 * 6; i += 256) g_flags[i] = 0;
        for (int i = tid; i < 2 * B; i += 256) { g_done[i] = 0; g_edone[i] = 0; }
        for (int i = tid; i < B; i += 256) g_acount[i] = 0;
        for (int i = tid; i < 2 * H * T; i += 256) {
            int t = i >> 7, j = i & 127;
            float s = 0.f;
#pragma unroll
            for (int u = 0; u < T; u++) s = fmaf(Wdense[j * T + u], Wfuse[u * T + t], s);
            g_weff1T[t * 2 * H + j] = s;
        }
        for (int i = tid; i < P * T; i += 256) {
            int t = i >> 5, d = i & 31;
            float s = 0.f;
#pragma unroll
            for (int p = 0; p < P; p++) s = fmaf(opw[p * P + d], Wfuse[(T + p) * T + t], s);
            g_weff2T[t * P + d] = s;
        }
        if (tid < T) {
            float s = 0.f;
#pragma unroll
            for (int p = 0; p < P; p++) s = fmaf(opb[p], Wfuse[(T + p) * T + tid], s);
            g_beff[tid] = s;
        }
        __threadfence();
    }
}

// ---------------- dummies ----------------
__global__ void dummy_kernel() {}

// ---------------- final mean ----------------
__global__ void final_kernel(float* __restrict__ out) {
    __shared__ float red[B];
    red[threadIdx.x] = g_nll[threadIdx.x];
    __syncthreads();
    for (int stp = 32; stp > 0; stp >>= 1) {
        if (threadIdx.x < stp) red[threadIdx.x] += red[threadIdx.x + stp];
        __syncthreads();
    }
    if (threadIdx.x == 0) out[0] = red[0] * (1.0f / B);
}

// ---------------- launch ----------------
extern "C" void kernel_launch(void* const* d_in, const int* in_sizes, int n_in,
                              void* d_out, int out_size) {
    const float* bert = (const float*)d_in[0];
    const float* input2 = (const float*)d_in[1];
    const int* targets = (const int*)d_in[2];
    const float* Wih_f = (const float*)d_in[3];
    const float* Whh_f = (const float*)d_in[4];
    const float* bih_f = (const float*)d_in[5];
    const float* bhh_f = (const float*)d_in[6];
    const float* Wih_b = (const float*)d_in[7];
    const float* Whh_b = (const float*)d_in[8];
    const float* bih_b = (const float*)d_in[9];
    const float* bhh_b = (const float*)d_in[10];
    const float* Wdense = (const float*)d_in[11];
    const float* in_proj_w = (const float*)d_in[12];
    const float* in_proj_b = (const float*)d_in[13];
    const float* out_proj_w = (const float*)d_in[14];
    const float* out_proj_b = (const float*)d_in[15];
    const float* Wfuse = (const float*)d_in[16];
    const float* crf_start = (const float*)d_in[17];
    const float* crf_end = (const float*)d_in[18];
    const float* crf_trans = (const float*)d_in[19];
    float* out = (float*)d_out;

    cudaFuncSetAttribute(mega_kernel, cudaFuncAttributeMaxDynamicSharedMemorySize, DSM_BYTES);

    prep_kernel<<<CVT_BLOCKS + QKV_BLOCKS + WCVT_BLOCKS + 1, 256>>>(
        bert, input2, in_proj_w, in_proj_b, Wih_f, Wih_b,
        Wdense, out_proj_w, out_proj_b, Wfuse);
    dummy_kernel<<<1, 32>>>();
    dummy_kernel<<<1, 32>>>();
    mega_kernel<<<TOTAL_BLOCKS, 256, DSM_BYTES>>>(bih_f, bih_b,
                                                  Whh_f, Whh_b, bhh_f, bhh_b,
                                                  targets, crf_start, crf_end, crf_trans);
    final_kernel<<<1, B>>>(out);
}

// round 16
// speedup vs baseline: 1.8246x; 1.8246x over previous
#include <cuda_runtime.h>
#include <cuda_bf16.h>
#include <math.h>
#include <stdint.h>

// Problem constants
#define B 64
#define S 512
#define E 768
#define H 64
#define G 192   // 3H
#define T 16
#define P 32

// ---------------- scratch ----------------
__device__ float g_xp_f[B * S * G];
__device__ float g_xp_b[B * S * G];
__device__ float g_lstm[B * S * 2 * H];
__device__ float g_qkv[B * S * 3 * P];
__device__ float g_av[B * S * P];
__device__ float g_emis[B * S * T];
__device__ float g_weff1T[T * 2 * H];
__device__ float g_weff2T[T * P];
__device__ float g_beff[T];
__device__ float g_nll[B];
__device__ int   g_flags[256 * 3];                 // (m_tile of 128 rows, n_tile of 128)
__device__ __nv_bfloat16 g_bert_h[B * S * E];
__device__ __nv_bfloat16 g_wh[2 * G * E];          // [384][768] combined Wih_f;Wih_b

__device__ __forceinline__ float sigmoidf_(float x) { return 1.0f / (1.0f + __expf(-x)); }
__device__ __forceinline__ float tanh_fast(float x) {
    float y; asm("tanh.approx.f32 %0, %1;" : "=f"(y) : "f"(x)); return y;
}
__device__ __forceinline__ void cp16(uint32_t s, const void* g) {
    asm volatile("cp.async.cg.shared.global [%0], [%1], 16;\n" :: "r"(s), "l"(g));
}
__device__ __forceinline__ void cp_commit() { asm volatile("cp.async.commit_group;\n"); }
template <int N> __device__ __forceinline__ void cp_wait() {
    asm volatile("cp.async.wait_group %0;\n" :: "n"(N));
}
__device__ __forceinline__ uint4 cvt8bf(float4 v0, float4 v1) {
    __nv_bfloat162 h0 = __floats2bfloat162_rn(v0.x, v0.y);
    __nv_bfloat162 h1 = __floats2bfloat162_rn(v0.z, v0.w);
    __nv_bfloat162 h2 = __floats2bfloat162_rn(v1.x, v1.y);
    __nv_bfloat162 h3 = __floats2bfloat162_rn(v1.z, v1.w);
    uint4 o;
    o.x = *(uint32_t*)&h0; o.y = *(uint32_t*)&h1;
    o.z = *(uint32_t*)&h2; o.w = *(uint32_t*)&h3;
    return o;
}

// =================================================================
// MEGA: GRU (0..127) + bf16 GEMM (128..895) + attention (896..1407)
// GEMM: xp = bert @ [Wih_f;Wih_b]^T + bias, bf16 mma m16n8k16
//       BM=128, BN=128, BK=32, 3-stage cp.async, 8 warps, warp 64x32
// =================================================================
#define KST 20                         // smem row stride in u32 (32 bf16 + pad)
#define STAGE_U (2 * 128 * KST)        // 5120 u32 per stage
#define DSM_BYTES (3 * STAGE_U * 4)    // 61440
#define GRU_BLOCKS 128
#define GEMM_BLOCKS 768
#define ATTN_OFF (GRU_BLOCKS + GEMM_BLOCKS)

__device__ __forceinline__ void poll2(int i0, int i1, int tid) {
    if (tid == 0) {
        volatile int* f = g_flags;
        while (f[i0] == 0) __nanosleep(64);
        while (f[i1] == 0) __nanosleep(64);
        __threadfence();
    }
    __syncthreads();
}

__global__ void __launch_bounds__(256, 2) mega_kernel(
    const float* __restrict__ bf, const float* __restrict__ bb,
    const float* __restrict__ Whh_f, const float* __restrict__ Whh_b,
    const float* __restrict__ bhh_f, const float* __restrict__ bhh_b)
{
    extern __shared__ __align__(16) float dsm[];
    const int tid = threadIdx.x;

    if (blockIdx.x < GRU_BLOCKS) {
        // ---------------- GRU (consumer) ----------------
        const int b = blockIdx.x >> 1;
        const int dir = blockIdx.x & 1;
        float* hsh = dsm;
        float* ghsh = dsm + 64;
        const bool act = (tid < G);

        float wreg[64];
        float bias = 0.f;
        if (act) {
            const float* Whh = dir ? Whh_b : Whh_f;
            const float4* wr = (const float4*)(Whh + (size_t)tid * H);
#pragma unroll
            for (int i = 0; i < 16; i++) {
                float4 v = __ldg(wr + i);
                wreg[4 * i] = v.x; wreg[4 * i + 1] = v.y;
                wreg[4 * i + 2] = v.z; wreg[4 * i + 3] = v.w;
            }
            bias = (dir ? bhh_b : bhh_f)[tid];
        }
        if (tid < H) hsh[tid] = 0.f;

        const int te0 = dir ? (S - 1) : 0;
        {
            int c0 = te0 >> 7;
            int base = (b * 4 + c0) * 3;
            poll2(base + (dir ? 1 : 0), base + (dir ? 2 : 1), tid);
        }

        const float* xp = (dir ? g_xp_b : g_xp_f) + (size_t)b * S * G;
        float xr = 0.f, xz = 0.f, xn = 0.f;
        if (tid < H) {
            const float* xrow = xp + (size_t)te0 * G;
            xr = xrow[tid]; xz = xrow[H + tid]; xn = xrow[2 * H + tid];
        }
        for (int t = 0; t < S; t++) {
            const int te = dir ? (S - 1 - t) : t;
            if (act) {
                float a0 = bias, a1 = 0.f, a2 = 0.f, a3 = 0.f;
                const float4* hv = (const float4*)hsh;
#pragma unroll
                for (int i = 0; i < 16; i++) {
                    float4 h4 = hv[i];
                    a0 = fmaf(wreg[4 * i], h4.x, a0);
                    a1 = fmaf(wreg[4 * i + 1], h4.y, a1);
                    a2 = fmaf(wreg[4 * i + 2], h4.z, a2);
                    a3 = fmaf(wreg[4 * i + 3], h4.w, a3);
                }
                ghsh[tid] = (a0 + a1) + (a2 + a3);
            }
            __syncthreads();
            if (((t + 1) & 127) == 0 && (t + 1) < S) {
                int ten = dir ? (S - 2 - t) : (t + 1);
                int c = ten >> 7;
                int base = (b * 4 + c) * 3;
                poll2(base + (dir ? 1 : 0), base + (dir ? 2 : 1), tid);
            }
            float nxr = 0.f, nxz = 0.f, nxn = 0.f;
            if (t < S - 1 && tid < H) {
                const float* xrow = xp + (size_t)(dir ? (S - 2 - t) : (t + 1)) * G;
                nxr = xrow[tid]; nxz = xrow[H + tid]; nxn = xrow[2 * H + tid];
            }
            if (tid < H) {
                float r = sigmoidf_(xr + ghsh[tid]);
                float z = sigmoidf_(xz + ghsh[H + tid]);
                float nw = tanh_fast(xn + r * ghsh[2 * H + tid]);
                float hn = (1.f - z) * nw + z * hsh[tid];
                hsh[tid] = hn;
                g_lstm[((size_t)b * S + te) * (2 * H) + dir * H + tid] = hn;
            }
            __syncthreads();
            xr = nxr; xz = nxz; xn = nxn;
        }
    } else if (blockIdx.x < ATTN_OFF) {
        // ---------------- bf16 GEMM (producer) ----------------
        const int bid = blockIdx.x - GRU_BLOCKS;
        const int nidx = bid % 3;
        const int r = bid / 3;            // 0..255
        const int p = r >> 7;             // phase 0..1
        const int q = r & 127;
        const int batch = q & 63;
        const int which = q >> 6;
        const int chunk = which ? (3 - p) : p;
        const int m_tile = batch * 4 + chunk;   // 0..255
        const int bm = m_tile * 128;
        const int bn = nidx * 128;

        const int w = tid >> 5, lane = tid & 31;
        const int wm = (w >> 2) * 64, wn = (w & 3) * 32;
        const int grp = lane >> 2, tig = lane & 3;

        const uint32_t smb = (uint32_t)__cvta_generic_to_shared(dsm);

        int lrow[2], lc[2];
        const __nv_bfloat16* aptr[2];
        const __nv_bfloat16* bptr[2];
#pragma unroll
        for (int i = 0; i < 2; i++) {
            int task = tid + 256 * i;
            lrow[i] = task >> 2; lc[i] = task & 3;
            aptr[i] = g_bert_h + (size_t)(bm + lrow[i]) * E + lc[i] * 8;
            bptr[i] = g_wh + (size_t)(bn + lrow[i]) * E + lc[i] * 8;
        }

        float acc[4][4][4];
#pragma unroll
        for (int mt = 0; mt < 4; mt++)
#pragma unroll
            for (int nt = 0; nt < 4; nt++)
#pragma unroll
                for (int d = 0; d < 4; d++) acc[mt][nt][d] = 0.0f;

#pragma unroll
        for (int s = 0; s < 2; s++) {
            uint32_t sb = smb + s * STAGE_U * 4;
#pragma unroll
            for (int i = 0; i < 2; i++) {
                cp16(sb + (lrow[i] * KST + lc[i] * 4) * 4, aptr[i] + s * 32);
                cp16(sb + ((128 + lrow[i]) * KST + lc[i] * 4) * 4, bptr[i] + s * 32);
            }
            cp_commit();
        }

        for (int kt = 0; kt < 24; kt++) {
            if (kt < 22) cp_wait<1>(); else cp_wait<0>();
            __syncthreads();
            if (kt + 2 < 24) {
                const int st = (kt + 2) % 3;
                const int kn = (kt + 2) * 32;
                uint32_t sb = smb + st * STAGE_U * 4;
#pragma unroll
                for (int i = 0; i < 2; i++) {
                    cp16(sb + (lrow[i] * KST + lc[i] * 4) * 4, aptr[i] + kn);
                    cp16(sb + ((128 + lrow[i]) * KST + lc[i] * 4) * 4, bptr[i] + kn);
                }
                cp_commit();
            }
            const int s = kt % 3;
            const uint32_t* As = (const uint32_t*)dsm + s * STAGE_U;
            const uint32_t* Bs = As + 128 * KST;
#pragma unroll
            for (int ks = 0; ks < 2; ks++) {
                const int ko = ks * 8;
                uint32_t afr[4][4], bfr[4][2];
#pragma unroll
                for (int mt = 0; mt < 4; mt++) {
                    const uint32_t* pa = As + (wm + mt * 16 + grp) * KST + ko + tig;
                    afr[mt][0] = pa[0];
                    afr[mt][1] = pa[8 * KST];
                    afr[mt][2] = pa[4];
                    afr[mt][3] = pa[8 * KST + 4];
                }
#pragma unroll
                for (int nt = 0; nt < 4; nt++) {
                    const uint32_t* pb = Bs + (wn + nt * 8 + grp) * KST + ko + tig;
                    bfr[nt][0] = pb[0];
                    bfr[nt][1] = pb[4];
                }
#pragma unroll
                for (int mt = 0; mt < 4; mt++)
#pragma unroll
                    for (int nt = 0; nt < 4; nt++) {
                        asm volatile(
                            "mma.sync.aligned.m16n8k16.row.col.f32.bf16.bf16.f32 "
                            "{%0,%1,%2,%3},{%4,%5,%6,%7},{%8,%9},{%0,%1,%2,%3};"
                            : "+f"(acc[mt][nt][0]), "+f"(acc[mt][nt][1]),
                              "+f"(acc[mt][nt][2]), "+f"(acc[mt][nt][3])
                            : "r"(afr[mt][0]), "r"(afr[mt][1]), "r"(afr[mt][2]), "r"(afr[mt][3]),
                              "r"(bfr[nt][0]), "r"(bfr[nt][1]));
                    }
            }
        }

#pragma unroll
        for (int mt = 0; mt < 4; mt++) {
            int m0 = bm + wm + mt * 16 + grp;
#pragma unroll
            for (int nt = 0; nt < 4; nt++) {
                int n = bn + wn + nt * 8 + 2 * tig;
                float* dst; const float* bp; int nn;
                if (n < G) { dst = g_xp_f; bp = bf; nn = n; }
                else       { dst = g_xp_b; bp = bb; nn = n - G; }
                float b0 = __ldg(bp + nn), b1 = __ldg(bp + nn + 1);
                *(float2*)(dst + (size_t)m0 * G + nn) =
                    make_float2(acc[mt][nt][0] + b0, acc[mt][nt][1] + b1);
                *(float2*)(dst + (size_t)(m0 + 8) * G + nn) =
                    make_float2(acc[mt][nt][2] + b0, acc[mt][nt][3] + b1);
            }
        }
        __syncthreads();
        if (tid == 0) {
            __threadfence();
            atomicExch(&g_flags[m_tile * 3 + nidx], 1);
        }
    } else {
        // ---------------- flash attention ----------------
        const int bid = blockIdx.x - ATTN_OFF;
        const int qt = bid & 7, b = bid >> 3;
        float* Ks = dsm;
        float* Vs = dsm + 64 * 36;
        float* psh = dsm + 2 * 64 * 36;
        const int q = tid >> 2, kg = tid & 3;
        const int qg = qt * 64 + q;
        const float scale = 0.17677669529663689f;

        float4 qv[8];
        {
            const float4* qp = (const float4*)(g_qkv + ((size_t)b * S + qg) * (3 * P));
#pragma unroll
            for (int i = 0; i < 8; i++) qv[i] = __ldg(qp + i);
        }
        float av0[4] = {0.f, 0.f, 0.f, 0.f}, av1[4] = {0.f, 0.f, 0.f, 0.f};
        float mrun = -1e30f, lrun = 0.f;

        for (int kt = 0; kt < 8; kt++) {
            __syncthreads();
            for (int i = tid; i < 64 * P; i += 256) {
                int row = i >> 5, d = i & 31;
                const float* base = g_qkv + ((size_t)b * S + kt * 64 + row) * (3 * P);
                Ks[row * 36 + d] = base[P + d];
                Vs[row * 36 + d] = base[2 * P + d];
            }
            __syncthreads();

            float sv[16];
            float tmax = -1e30f;
#pragma unroll
            for (int kl = 0; kl < 16; kl++) {
                int k = kg + kl * 4;
                const float4* kr = (const float4*)(Ks + k * 36);
                float d0 = 0.f, d1 = 0.f, d2 = 0.f, d3 = 0.f;
#pragma unroll
                for (int i = 0; i < 8; i += 4) {
                    float4 k0 = kr[i], k1 = kr[i + 1], k2 = kr[i + 2], k3 = kr[i + 3];
                    d0 = fmaf(qv[i].x, k0.x, d0); d0 = fmaf(qv[i].y, k0.y, d0);
                    d0 = fmaf(qv[i].z, k0.z, d0); d0 = fmaf(qv[i].w, k0.w, d0);
                    d1 = fmaf(qv[i+1].x, k1.x, d1); d1 = fmaf(qv[i+1].y, k1.y, d1);
                    d1 = fmaf(qv[i+1].z, k1.z, d1); d1 = fmaf(qv[i+1].w, k1.w, d1);
                    d2 = fmaf(qv[i+2].x, k2.x, d2); d2 = fmaf(qv[i+2].y, k2.y, d2);
                    d2 = fmaf(qv[i+2].z, k2.z, d2); d2 = fmaf(qv[i+2].w, k2.w, d2);
                    d3 = fmaf(qv[i+3].x, k3.x, d3); d3 = fmaf(qv[i+3].y, k3.y, d3);
                    d3 = fmaf(qv[i+3].z, k3.z, d3); d3 = fmaf(qv[i+3].w, k3.w, d3);
                }
                sv[kl] = ((d0 + d1) + (d2 + d3)) * scale;
                tmax = fmaxf(tmax, sv[kl]);
            }
            tmax = fmaxf(tmax, __shfl_xor_sync(0xffffffffu, tmax, 1));
            tmax = fmaxf(tmax, __shfl_xor_sync(0xffffffffu, tmax, 2));
            float mnew = fmaxf(mrun, tmax);
            float corr = __expf(mrun - mnew);
            float tsum = 0.f;
#pragma unroll
            for (int kl = 0; kl < 16; kl++) {
                float e = __expf(sv[kl] - mnew);
                psh[q * 68 + kg + kl * 4] = e;
                tsum += e;
            }
            tsum += __shfl_xor_sync(0xffffffffu, tsum, 1);
            tsum += __shfl_xor_sync(0xffffffffu, tsum, 2);
            lrun = lrun * corr + tsum;
            mrun = mnew;
#pragma unroll
            for (int j = 0; j < 4; j++) { av0[j] *= corr; av1[j] *= corr; }
            __syncwarp();
#pragma unroll 4
            for (int k = 0; k < 64; k++) {
                float pv = psh[q * 68 + k];
                const float4* vr = (const float4*)(Vs + k * 36 + kg * 8);
                float4 v0 = vr[0], v1 = vr[1];
                av0[0] = fmaf(pv, v0.x, av0[0]); av0[1] = fmaf(pv, v0.y, av0[1]);
                av0[2] = fmaf(pv, v0.z, av0[2]); av0[3] = fmaf(pv, v0.w, av0[3]);
                av1[0] = fmaf(pv, v1.x, av1[0]); av1[1] = fmaf(pv, v1.y, av1[1]);
                av1[2] = fmaf(pv, v1.z, av1[2]); av1[3] = fmaf(pv, v1.w, av1[3]);
            }
            __syncwarp();
        }
        float inv = 1.0f / lrun;
        float* op = g_av + ((size_t)b * S + qg) * P + kg * 8;
        *(float4*)(op) = make_float4(av0[0] * inv, av0[1] * inv, av0[2] * inv, av0[3] * inv);
        *(float4*)(op + 4) = make_float4(av1[0] * inv, av1[1] * inv, av1[2] * inv, av1[3] * inv);
    }
}

// =================================================================
// PREP v2: wide cvt (64 floats/thread) + smem-tiled qkv + weff/flags
// grid: [0,1536) bert cvt | [1536,2048) qkv | [2048,2066) wcvt | 2066 weff
// =================================================================
#define CVT2_BLOCKS 1536
#define QKV2_BLOCKS 512
#define WCVT2_BLOCKS 18
__global__ void __launch_bounds__(256) prep_kernel(
    const float* __restrict__ bert,
    const float* __restrict__ in2, const float* __restrict__ W,
    const float* __restrict__ bias,
    const float* __restrict__ Wf, const float* __restrict__ Wb,
    const float* __restrict__ Wdense, const float* __restrict__ opw,
    const float* __restrict__ opb, const float* __restrict__ Wfuse)
{
    const int bx = blockIdx.x;
    const int tid = threadIdx.x;
    if (bx < CVT2_BLOCKS) {
        // bert -> bf16, 16384 floats per block, 64 per thread
        size_t base = (size_t)bx * 16384 + tid * 8;
#pragma unroll
        for (int it = 0; it < 8; it++) {
            size_t o = base + (size_t)it * 2048;
            float4 v0 = *(const float4*)(bert + o);
            float4 v1 = *(const float4*)(bert + o + 4);
            *(uint4*)(g_bert_h + o) = cvt8bf(v0, v1);
        }
    } else if (bx < CVT2_BLOCKS + QKV2_BLOCKS) {
        // qkv, smem-tiled: 64 m-rows per block
        __shared__ float xs[64 * 33];
        __shared__ float ws[96 * 32];
        __shared__ float bs[96];
        const int m0 = (bx - CVT2_BLOCKS) * 64;
        for (int i = tid; i < 64 * 32; i += 256) {
            int row = i >> 5, col = i & 31;
            xs[row * 33 + col] = in2[(size_t)(m0 + row) * P + col];
        }
        for (int i = tid; i < 96 * 32; i += 256) ws[i] = W[i];
        if (tid < 96) bs[tid] = bias[tid];
        __syncthreads();

        const int m = tid >> 2;
        const int ng = tid & 3;
        float x[32];
#pragma unroll
        for (int k = 0; k < 32; k++) x[k] = xs[m * 33 + k];
        float* orow = g_qkv + (size_t)(m0 + m) * (3 * P);
#pragma unroll 4
        for (int jn = 0; jn < 24; jn++) {
            int n = ng * 24 + jn;
            const float4* wv = (const float4*)(ws + n * 32);
            float acc = bs[n];
#pragma unroll
            for (int k4 = 0; k4 < 8; k4++) {
                float4 wq = wv[k4];
                acc = fmaf(x[4 * k4], wq.x, acc);
                acc = fmaf(x[4 * k4 + 1], wq.y, acc);
                acc = fmaf(x[4 * k4 + 2], wq.z, acc);
                acc = fmaf(x[4 * k4 + 3], wq.w, acc);
            }
            orow[n] = acc;
        }
    } else if (bx < CVT2_BLOCKS + QKV2_BLOCKS + WCVT2_BLOCKS) {
        // Wih -> bf16, 16384 floats per block
        const int half = G * E;   // 147456
        int base = (bx - CVT2_BLOCKS - QKV2_BLOCKS) * 16384 + tid * 8;
#pragma unroll
        for (int it = 0; it < 8; it++) {
            int o = base + it * 2048;
            const float* src = (o < half) ? (Wf + o) : (Wb + o - half);
            float4 v0 = *(const float4*)(src);
            float4 v1 = *(const float4*)(src + 4);
            *(uint4*)(g_wh + o) = cvt8bf(v0, v1);
        }
    } else {
        for (int i = tid; i < 256 * 3; i += 256) g_flags[i] = 0;
        for (int i = tid; i < 2 * H * T; i += 256) {
            int t = i >> 7, j = i & 127;
            float s = 0.f;
#pragma unroll
            for (int u = 0; u < T; u++) s = fmaf(Wdense[j * T + u], Wfuse[u * T + t], s);
            g_weff1T[t * 2 * H + j] = s;
        }
        for (int i = tid; i < P * T; i += 256) {
            int t = i >> 5, d = i & 31;
            float s = 0.f;
#pragma unroll
            for (int p = 0; p < P; p++) s = fmaf(opw[p * P + d], Wfuse[(T + p) * T + t], s);
            g_weff2T[t * P + d] = s;
        }
        if (tid < T) {
            float s = 0.f;
#pragma unroll
            for (int p = 0; p < P; p++) s = fmaf(opb[p], Wfuse[(T + p) * T + tid], s);
            g_beff[tid] = s;
        }
        __threadfence();
    }
}

// ---------------- emissions ----------------
__global__ void __launch_bounds__(256) emis_kernel() {
    __shared__ float lrow[16 * 2 * H];
    __shared__ float arow[16 * P];
    __shared__ float w1s[T * 133];
    __shared__ float w2s[T * 37];
    __shared__ float bes[T];
    const int tid = threadIdx.x;
    const int r0 = blockIdx.x * 16;

    for (int i = tid; i < 16 * 2 * H; i += 256) lrow[i] = g_lstm[(size_t)r0 * 2 * H + i];
    for (int i = tid; i < 16 * P; i += 256) arow[i] = g_av[(size_t)r0 * P + i];
    for (int i = tid; i < T * 2 * H; i += 256) {
        int t = i >> 7, j = i & 127;
        w1s[t * 133 + j] = g_weff1T[i];
    }
    for (int i = tid; i < T * P; i += 256) {
        int t = i >> 5, d = i & 31;
        w2s[t * 37 + d] = g_weff2T[i];
    }
    if (tid < T) bes[tid] = g_beff[tid];
    __syncthreads();

    const int rr = tid >> 4;
    const int t = tid & 15;
    float acc = bes[t];
    const float* lr = lrow + rr * 2 * H;
    const float* w1 = w1s + t * 133;
#pragma unroll
    for (int i = 0; i < 2 * H; i += 4) {
        acc = fmaf(lr[i], w1[i], acc);
        acc = fmaf(lr[i + 1], w1[i + 1], acc);
        acc = fmaf(lr[i + 2], w1[i + 2], acc);
        acc = fmaf(lr[i + 3], w1[i + 3], acc);
    }
    const float* ar = arow + rr * P;
    const float* w2 = w2s + t * 37;
#pragma unroll
    for (int i = 0; i < P; i += 4) {
        acc = fmaf(ar[i], w2[i], acc);
        acc = fmaf(ar[i + 1], w2[i + 1], acc);
        acc = fmaf(ar[i + 2], w2[i + 2], acc);
        acc = fmaf(ar[i + 3], w2[i + 3], acc);
    }
    g_emis[(size_t)(r0 + rr) * T + t] = acc;
}

// =================================================================
// CRF: warp 0 forward to t=255, warp 1 backward to t=255, LSE merge
// =================================================================
__global__ void __launch_bounds__(64) crf_kernel(
    const int* __restrict__ targets, const float* __restrict__ crf_start,
    const float* __restrict__ crf_end, const float* __restrict__ crf_trans)
{
    __shared__ float tr[T * 17];
    __shared__ float alpha_s[T];
    __shared__ float beta_s[T];
    __shared__ float numw[2];
    const int b = blockIdx.x;
    const int tid = threadIdx.x;
    const int wid = tid >> 5, lane = tid & 31;
    const int j = lane & 15, half = lane >> 4;

    for (int i = tid; i < T * T; i += 64) tr[(i >> 4) * 17 + (i & 15)] = crf_trans[i];
    __syncthreads();

    const int* tg = targets + (size_t)b * S;
    {
        float num = 0.f;
        for (int t = tid; t < S; t += 64) {
            int cur = tg[t];
            num += g_emis[((size_t)b * S + t) * T + cur];
            if (t < S - 1) num += tr[cur * 17 + tg[t + 1]];
        }
#pragma unroll
        for (int o = 16; o > 0; o >>= 1) num += __shfl_xor_sync(0xffffffffu, num, o);
        if (lane == 0) numw[wid] = num;
    }

    const float* em_b = g_emis + (size_t)b * S * T;
    const int src_base = half * 24;

    if (wid == 0) {
        float Ereg[8];
#pragma unroll
        for (int k = 0; k < 8; k++) Ereg[k] = __expf(tr[(half * 8 + k) * 17 + j]);
        float a = crf_start[j] + em_b[j];
        float em = em_b[T + j];
        for (int t = 1; t <= 255; t++) {
            float em_next = em_b[(t + 1) * T + j];
            float anchor = __shfl_sync(0xffffffffu, a, 0);
            float e = __expf(a - anchor);
            float acc0 = 0.f, acc1 = 0.f;
#pragma unroll
            for (int i = 0; i < 8; i += 2) {
                float e0 = __shfl_sync(0xffffffffu, e, src_base + i);
                float e1 = __shfl_sync(0xffffffffu, e, src_base + i + 1);
                acc0 = fmaf(e0, Ereg[i], acc0);
                acc1 = fmaf(e1, Ereg[i + 1], acc1);
            }
            float acc = acc0 + acc1;
            acc += __shfl_xor_sync(0xffffffffu, acc, 16);
            a = anchor + __logf(acc) + em;
            em = em_next;
        }
        if (half == 0) alpha_s[j] = a;
    } else {
        float EregB[8];
#pragma unroll
        for (int i2 = 0; i2 < 8; i2++) EregB[i2] = __expf(tr[j * 17 + half * 8 + i2]);
        float bt = crf_end[j];
        float em1 = em_b[511 * T + j];
        for (int t = 510; t >= 255; t--) {
            float em_next = (t > 255) ? em_b[t * T + j] : 0.f;
            float g = bt + em1;
            float anchor = __shfl_sync(0xffffffffu, g, 0);
            float e = __expf(g - anchor);
            float acc0 = 0.f, acc1 = 0.f;
#pragma unroll
            for (int i2 = 0; i2 < 8; i2 += 2) {
                float e0 = __shfl_sync(0xffffffffu, e, src_base + i2);
                float e1 = __shfl_sync(0xffffffffu, e, src_base + i2 + 1);
                acc0 = fmaf(e0, EregB[i2], acc0);
                acc1 = fmaf(e1, EregB[i2 + 1], acc1);
            }
            float acc = acc0 + acc1;
            acc += __shfl_xor_sync(0xffffffffu, acc, 16);
            bt = anchor + __logf(acc);
            em1 = em_next;
        }
        if (half == 0) beta_s[j] = bt;
    }
    __syncthreads();

    if (wid == 0) {
        float v = (lane < T) ? (alpha_s[lane] + beta_s[lane]) : -1e30f;
        float m = v;
#pragma unroll
        for (int o = 16; o > 0; o >>= 1) m = fmaxf(m, __shfl_xor_sync(0xffffffffu, m, o));
        float e = (lane < T) ? __expf(v - m) : 0.f;
#pragma unroll
        for (int o = 16; o > 0; o >>= 1) e += __shfl_xor_sync(0xffffffffu, e, o);
        if (lane == 0) {
            float s_num = numw[0] + numw[1] + crf_start[tg[0]] + crf_end[tg[S - 1]];
            g_nll[b] = (m + __logf(e)) - s_num;
        }
    }
}

// ---------------- final mean ----------------
__global__ void final_kernel(float* __restrict__ out) {
    __shared__ float red[B];
    red[threadIdx.x] = g_nll[threadIdx.x];
    __syncthreads();
    for (int stp = 32; stp > 0; stp >>= 1) {
        if (threadIdx.x < stp) red[threadIdx.x] += red[threadIdx.x + stp];
        __syncthreads();
    }
    if (threadIdx.x == 0) out[0] = red[0] * (1.0f / B);
}

// ---------------- launch ----------------
extern "C" void kernel_launch(void* const* d_in, const int* in_sizes, int n_in,
                              void* d_out, int out_size) {
    const float* bert = (const float*)d_in[0];
    const float* input2 = (const float*)d_in[1];
    const int* targets = (const int*)d_in[2];
    const float* Wih_f = (const float*)d_in[3];
    const float* Whh_f = (const float*)d_in[4];
    const float* bih_f = (const float*)d_in[5];
    const float* bhh_f = (const float*)d_in[6];
    const float* Wih_b = (const float*)d_in[7];
    const float* Whh_b = (const float*)d_in[8];
    const float* bih_b = (const float*)d_in[9];
    const float* bhh_b = (const float*)d_in[10];
    const float* Wdense = (const float*)d_in[11];
    const float* in_proj_w = (const float*)d_in[12];
    const float* in_proj_b = (const float*)d_in[13];
    const float* out_proj_w = (const float*)d_in[14];
    const float* out_proj_b = (const float*)d_in[15];
    const float* Wfuse = (const float*)d_in[16];
    const float* crf_start = (const float*)d_in[17];
    const float* crf_end = (const float*)d_in[18];
    const float* crf_trans = (const float*)d_in[19];
    float* out = (float*)d_out;

    cudaFuncSetAttribute(mega_kernel, cudaFuncAttributeMaxDynamicSharedMemorySize, DSM_BYTES);

    // prep v2: wide bf16 conversions + smem-tiled qkv + weff + flag reset
    prep_kernel<<<CVT2_BLOCKS + QKV2_BLOCKS + WCVT2_BLOCKS + 1, 256>>>(
        bert, input2, in_proj_w, in_proj_b, Wih_f, Wih_b,
        Wdense, out_proj_w, out_proj_b, Wfuse);
    // GRU (0..127) + GEMM (128..895) + attention (896..1407)
    mega_kernel<<<ATTN_OFF + 512, 256, DSM_BYTES>>>(bih_f, bih_b,
                                                    Whh_f, Whh_b, bhh_f, bhh_b);
    // emissions
    emis_kernel<<<(B * S) / 16, 256>>>();
    // CRF (forward/backward split)
    crf_kernel<<<B, 64>>>(targets, crf_start, crf_end, crf_trans);
    // mean
    final_kernel<<<1, B>>>(out);
}

// round 17
// speedup vs baseline: 1.9214x; 1.0530x over previous
#include <cuda_runtime.h>
#include <cuda_bf16.h>
#include <math.h>
#include <stdint.h>

// Problem constants
#define B 64
#define S 512
#define E 768
#define H 64
#define G 192   // 3H
#define T 16
#define P 32

// ---------------- scratch ----------------
__device__ float g_xp_f[B * S * G];
__device__ float g_xp_b[B * S * G];
__device__ float g_lstm[B * S * 2 * H];
__device__ float g_qkv[B * S * 3 * P];
__device__ float g_av[B * S * P];
__device__ float g_emis[B * S * T];
__device__ float g_weff1T[T * 2 * H];
__device__ float g_weff2T[T * P];
__device__ float g_beff[T];
__device__ int   g_flags[256 * 3];                 // (m_tile of 128 rows, n_tile of 128)
__device__ __nv_bfloat16 g_bert_h[B * S * E];
__device__ __nv_bfloat16 g_wh[2 * G * E];          // [384][768] combined Wih_f;Wih_b

__device__ __forceinline__ float sigmoidf_(float x) { return 1.0f / (1.0f + __expf(-x)); }
__device__ __forceinline__ float tanh_fast(float x) {
    float y; asm("tanh.approx.f32 %0, %1;" : "=f"(y) : "f"(x)); return y;
}
__device__ __forceinline__ void cp16(uint32_t s, const void* g) {
    asm volatile("cp.async.cg.shared.global [%0], [%1], 16;\n" :: "r"(s), "l"(g));
}
__device__ __forceinline__ void cp_commit() { asm volatile("cp.async.commit_group;\n"); }
template <int N> __device__ __forceinline__ void cp_wait() {
    asm volatile("cp.async.wait_group %0;\n" :: "n"(N));
}
__device__ __forceinline__ uint4 cvt8bf(float4 v0, float4 v1) {
    __nv_bfloat162 h0 = __floats2bfloat162_rn(v0.x, v0.y);
    __nv_bfloat162 h1 = __floats2bfloat162_rn(v0.z, v0.w);
    __nv_bfloat162 h2 = __floats2bfloat162_rn(v1.x, v1.y);
    __nv_bfloat162 h3 = __floats2bfloat162_rn(v1.z, v1.w);
    uint4 o;
    o.x = *(uint32_t*)&h0; o.y = *(uint32_t*)&h1;
    o.z = *(uint32_t*)&h2; o.w = *(uint32_t*)&h3;
    return o;
}

// =================================================================
// MEGA: GRU (0..127) + bf16 GEMM (128..895) + attention (896..1407)
// =================================================================
#define KST 20
#define STAGE_U (2 * 128 * KST)
#define DSM_BYTES (3 * STAGE_U * 4)    // 61440
#define GRU_BLOCKS 128
#define GEMM_BLOCKS 768
#define ATTN_OFF (GRU_BLOCKS + GEMM_BLOCKS)

__device__ __forceinline__ void poll2(int i0, int i1, int tid) {
    if (tid == 0) {
        volatile int* f = g_flags;
        while (f[i0] == 0) __nanosleep(64);
        while (f[i1] == 0) __nanosleep(64);
        __threadfence();
    }
    __syncthreads();
}

__global__ void __launch_bounds__(256, 2) mega_kernel(
    const float* __restrict__ bf, const float* __restrict__ bb,
    const float* __restrict__ Whh_f, const float* __restrict__ Whh_b,
    const float* __restrict__ bhh_f, const float* __restrict__ bhh_b)
{
    extern __shared__ __align__(16) float dsm[];
    const int tid = threadIdx.x;

    if (blockIdx.x < GRU_BLOCKS) {
        // ---------------- GRU (consumer) ----------------
        const int b = blockIdx.x >> 1;
        const int dir = blockIdx.x & 1;
        float* hsh = dsm;
        float* ghsh = dsm + 64;
        const bool act = (tid < G);

        float wreg[64];
        float bias = 0.f;
        if (act) {
            const float* Whh = dir ? Whh_b : Whh_f;
            const float4* wr = (const float4*)(Whh + (size_t)tid * H);
#pragma unroll
            for (int i = 0; i < 16; i++) {
                float4 v = __ldg(wr + i);
                wreg[4 * i] = v.x; wreg[4 * i + 1] = v.y;
                wreg[4 * i + 2] = v.z; wreg[4 * i + 3] = v.w;
            }
            bias = (dir ? bhh_b : bhh_f)[tid];
        }
        if (tid < H) hsh[tid] = 0.f;

        const int te0 = dir ? (S - 1) : 0;
        {
            int c0 = te0 >> 7;
            int base = (b * 4 + c0) * 3;
            poll2(base + (dir ? 1 : 0), base + (dir ? 2 : 1), tid);
        }

        const float* xp = (dir ? g_xp_b : g_xp_f) + (size_t)b * S * G;
        float xr = 0.f, xz = 0.f, xn = 0.f;
        if (tid < H) {
            const float* xrow = xp + (size_t)te0 * G;
            xr = xrow[tid]; xz = xrow[H + tid]; xn = xrow[2 * H + tid];
        }
        for (int t = 0; t < S; t++) {
            const int te = dir ? (S - 1 - t) : t;
            if (act) {
                float a0 = bias, a1 = 0.f, a2 = 0.f, a3 = 0.f;
                const float4* hv = (const float4*)hsh;
#pragma unroll
                for (int i = 0; i < 16; i++) {
                    float4 h4 = hv[i];
                    a0 = fmaf(wreg[4 * i], h4.x, a0);
                    a1 = fmaf(wreg[4 * i + 1], h4.y, a1);
                    a2 = fmaf(wreg[4 * i + 2], h4.z, a2);
                    a3 = fmaf(wreg[4 * i + 3], h4.w, a3);
                }
                ghsh[tid] = (a0 + a1) + (a2 + a3);
            }
            __syncthreads();
            if (((t + 1) & 127) == 0 && (t + 1) < S) {
                int ten = dir ? (S - 2 - t) : (t + 1);
                int c = ten >> 7;
                int base = (b * 4 + c) * 3;
                poll2(base + (dir ? 1 : 0), base + (dir ? 2 : 1), tid);
            }
            float nxr = 0.f, nxz = 0.f, nxn = 0.f;
            if (t < S - 1 && tid < H) {
                const float* xrow = xp + (size_t)(dir ? (S - 2 - t) : (t + 1)) * G;
                nxr = xrow[tid]; nxz = xrow[H + tid]; nxn = xrow[2 * H + tid];
            }
            if (tid < H) {
                float r = sigmoidf_(xr + ghsh[tid]);
                float z = sigmoidf_(xz + ghsh[H + tid]);
                float nw = tanh_fast(xn + r * ghsh[2 * H + tid]);
                float hn = (1.f - z) * nw + z * hsh[tid];
                hsh[tid] = hn;
                g_lstm[((size_t)b * S + te) * (2 * H) + dir * H + tid] = hn;
            }
            __syncthreads();
            xr = nxr; xz = nxz; xn = nxn;
        }
    } else if (blockIdx.x < ATTN_OFF) {
        // ---------------- bf16 GEMM (producer) ----------------
        const int bid = blockIdx.x - GRU_BLOCKS;
        const int nidx = bid % 3;
        const int r = bid / 3;
        const int p = r >> 7;
        const int q = r & 127;
        const int batch = q & 63;
        const int which = q >> 6;
        const int chunk = which ? (3 - p) : p;
        const int m_tile = batch * 4 + chunk;
        const int bm = m_tile * 128;
        const int bn = nidx * 128;

        const int w = tid >> 5, lane = tid & 31;
        const int wm = (w >> 2) * 64, wn = (w & 3) * 32;
        const int grp = lane >> 2, tig = lane & 3;

        const uint32_t smb = (uint32_t)__cvta_generic_to_shared(dsm);

        int lrow[2], lc[2];
        const __nv_bfloat16* aptr[2];
        const __nv_bfloat16* bptr[2];
#pragma unroll
        for (int i = 0; i < 2; i++) {
            int task = tid + 256 * i;
            lrow[i] = task >> 2; lc[i] = task & 3;
            aptr[i] = g_bert_h + (size_t)(bm + lrow[i]) * E + lc[i] * 8;
            bptr[i] = g_wh + (size_t)(bn + lrow[i]) * E + lc[i] * 8;
        }

        float acc[4][4][4];
#pragma unroll
        for (int mt = 0; mt < 4; mt++)
#pragma unroll
            for (int nt = 0; nt < 4; nt++)
#pragma unroll
                for (int d = 0; d < 4; d++) acc[mt][nt][d] = 0.0f;

#pragma unroll
        for (int s = 0; s < 2; s++) {
            uint32_t sb = smb + s * STAGE_U * 4;
#pragma unroll
            for (int i = 0; i < 2; i++) {
                cp16(sb + (lrow[i] * KST + lc[i] * 4) * 4, aptr[i] + s * 32);
                cp16(sb + ((128 + lrow[i]) * KST + lc[i] * 4) * 4, bptr[i] + s * 32);
            }
            cp_commit();
        }

        for (int kt = 0; kt < 24; kt++) {
            if (kt < 22) cp_wait<1>(); else cp_wait<0>();
            __syncthreads();
            if (kt + 2 < 24) {
                const int st = (kt + 2) % 3;
                const int kn = (kt + 2) * 32;
                uint32_t sb = smb + st * STAGE_U * 4;
#pragma unroll
                for (int i = 0; i < 2; i++) {
                    cp16(sb + (lrow[i] * KST + lc[i] * 4) * 4, aptr[i] + kn);
                    cp16(sb + ((128 + lrow[i]) * KST + lc[i] * 4) * 4, bptr[i] + kn);
                }
                cp_commit();
            }
            const int s = kt % 3;
            const uint32_t* As = (const uint32_t*)dsm + s * STAGE_U;
            const uint32_t* Bs = As + 128 * KST;
#pragma unroll
            for (int ks = 0; ks < 2; ks++) {
                const int ko = ks * 8;
                uint32_t afr[4][4], bfr[4][2];
#pragma unroll
                for (int mt = 0; mt < 4; mt++) {
                    const uint32_t* pa = As + (wm + mt * 16 + grp) * KST + ko + tig;
                    afr[mt][0] = pa[0];
                    afr[mt][1] = pa[8 * KST];
                    afr[mt][2] = pa[4];
                    afr[mt][3] = pa[8 * KST + 4];
                }
#pragma unroll
                for (int nt = 0; nt < 4; nt++) {
                    const uint32_t* pb = Bs + (wn + nt * 8 + grp) * KST + ko + tig;
                    bfr[nt][0] = pb[0];
                    bfr[nt][1] = pb[4];
                }
#pragma unroll
                for (int mt = 0; mt < 4; mt++)
#pragma unroll
                    for (int nt = 0; nt < 4; nt++) {
                        asm volatile(
                            "mma.sync.aligned.m16n8k16.row.col.f32.bf16.bf16.f32 "
                            "{%0,%1,%2,%3},{%4,%5,%6,%7},{%8,%9},{%0,%1,%2,%3};"
                            : "+f"(acc[mt][nt][0]), "+f"(acc[mt][nt][1]),
                              "+f"(acc[mt][nt][2]), "+f"(acc[mt][nt][3])
                            : "r"(afr[mt][0]), "r"(afr[mt][1]), "r"(afr[mt][2]), "r"(afr[mt][3]),
                              "r"(bfr[nt][0]), "r"(bfr[nt][1]));
                    }
            }
        }

#pragma unroll
        for (int mt = 0; mt < 4; mt++) {
            int m0 = bm + wm + mt * 16 + grp;
#pragma unroll
            for (int nt = 0; nt < 4; nt++) {
                int n = bn + wn + nt * 8 + 2 * tig;
                float* dst; const float* bp; int nn;
                if (n < G) { dst = g_xp_f; bp = bf; nn = n; }
                else       { dst = g_xp_b; bp = bb; nn = n - G; }
                float b0 = __ldg(bp + nn), b1 = __ldg(bp + nn + 1);
                *(float2*)(dst + (size_t)m0 * G + nn) =
                    make_float2(acc[mt][nt][0] + b0, acc[mt][nt][1] + b1);
                *(float2*)(dst + (size_t)(m0 + 8) * G + nn) =
                    make_float2(acc[mt][nt][2] + b0, acc[mt][nt][3] + b1);
            }
        }
        __syncthreads();
        if (tid == 0) {
            __threadfence();
            atomicExch(&g_flags[m_tile * 3 + nidx], 1);
        }
    } else {
        // ---------------- flash attention ----------------
        const int bid = blockIdx.x - ATTN_OFF;
        const int qt = bid & 7, b = bid >> 3;
        float* Ks = dsm;
        float* Vs = dsm + 64 * 36;
        float* psh = dsm + 2 * 64 * 36;
        const int q = tid >> 2, kg = tid & 3;
        const int qg = qt * 64 + q;
        const float scale = 0.17677669529663689f;

        float4 qv[8];
        {
            const float4* qp = (const float4*)(g_qkv + ((size_t)b * S + qg) * (3 * P));
#pragma unroll
            for (int i = 0; i < 8; i++) qv[i] = __ldg(qp + i);
        }
        float av0[4] = {0.f, 0.f, 0.f, 0.f}, av1[4] = {0.f, 0.f, 0.f, 0.f};
        float mrun = -1e30f, lrun = 0.f;

        for (int kt = 0; kt < 8; kt++) {
            __syncthreads();
            for (int i = tid; i < 64 * P; i += 256) {
                int row = i >> 5, d = i & 31;
                const float* base = g_qkv + ((size_t)b * S + kt * 64 + row) * (3 * P);
                Ks[row * 36 + d] = base[P + d];
                Vs[row * 36 + d] = base[2 * P + d];
            }
            __syncthreads();

            float sv[16];
            float tmax = -1e30f;
#pragma unroll
            for (int kl = 0; kl < 16; kl++) {
                int k = kg + kl * 4;
                const float4* kr = (const float4*)(Ks + k * 36);
                float d0 = 0.f, d1 = 0.f, d2 = 0.f, d3 = 0.f;
#pragma unroll
                for (int i = 0; i < 8; i += 4) {
                    float4 k0 = kr[i], k1 = kr[i + 1], k2 = kr[i + 2], k3 = kr[i + 3];
                    d0 = fmaf(qv[i].x, k0.x, d0); d0 = fmaf(qv[i].y, k0.y, d0);
                    d0 = fmaf(qv[i].z, k0.z, d0); d0 = fmaf(qv[i].w, k0.w, d0);
                    d1 = fmaf(qv[i+1].x, k1.x, d1); d1 = fmaf(qv[i+1].y, k1.y, d1);
                    d1 = fmaf(qv[i+1].z, k1.z, d1); d1 = fmaf(qv[i+1].w, k1.w, d1);
                    d2 = fmaf(qv[i+2].x, k2.x, d2); d2 = fmaf(qv[i+2].y, k2.y, d2);
                    d2 = fmaf(qv[i+2].z, k2.z, d2); d2 = fmaf(qv[i+2].w, k2.w, d2);
                    d3 = fmaf(qv[i+3].x, k3.x, d3); d3 = fmaf(qv[i+3].y, k3.y, d3);
                    d3 = fmaf(qv[i+3].z, k3.z, d3); d3 = fmaf(qv[i+3].w, k3.w, d3);
                }
                sv[kl] = ((d0 + d1) + (d2 + d3)) * scale;
                tmax = fmaxf(tmax, sv[kl]);
            }
            tmax = fmaxf(tmax, __shfl_xor_sync(0xffffffffu, tmax, 1));
            tmax = fmaxf(tmax, __shfl_xor_sync(0xffffffffu, tmax, 2));
            float mnew = fmaxf(mrun, tmax);
            float corr = __expf(mrun - mnew);
            float tsum = 0.f;
#pragma unroll
            for (int kl = 0; kl < 16; kl++) {
                float e = __expf(sv[kl] - mnew);
                psh[q * 68 + kg + kl * 4] = e;
                tsum += e;
            }
            tsum += __shfl_xor_sync(0xffffffffu, tsum, 1);
            tsum += __shfl_xor_sync(0xffffffffu, tsum, 2);
            lrun = lrun * corr + tsum;
            mrun = mnew;
#pragma unroll
            for (int j = 0; j < 4; j++) { av0[j] *= corr; av1[j] *= corr; }
            __syncwarp();
#pragma unroll 4
            for (int k = 0; k < 64; k++) {
                float pv = psh[q * 68 + k];
                const float4* vr = (const float4*)(Vs + k * 36 + kg * 8);
                float4 v0 = vr[0], v1 = vr[1];
                av0[0] = fmaf(pv, v0.x, av0[0]); av0[1] = fmaf(pv, v0.y, av0[1]);
                av0[2] = fmaf(pv, v0.z, av0[2]); av0[3] = fmaf(pv, v0.w, av0[3]);
                av1[0] = fmaf(pv, v1.x, av1[0]); av1[1] = fmaf(pv, v1.y, av1[1]);
                av1[2] = fmaf(pv, v1.z, av1[2]); av1[3] = fmaf(pv, v1.w, av1[3]);
            }
            __syncwarp();
        }
        float inv = 1.0f / lrun;
        float* op = g_av + ((size_t)b * S + qg) * P + kg * 8;
        *(float4*)(op) = make_float4(av0[0] * inv, av0[1] * inv, av0[2] * inv, av0[3] * inv);
        *(float4*)(op + 4) = make_float4(av1[0] * inv, av1[1] * inv, av1[2] * inv, av1[3] * inv);
    }
}

// =================================================================
// PREP v2: wide cvt + smem-tiled qkv + weff/flags + out zero
// =================================================================
#define CVT2_BLOCKS 1536
#define QKV2_BLOCKS 512
#define WCVT2_BLOCKS 18
__global__ void __launch_bounds__(256) prep_kernel(
    const float* __restrict__ bert,
    const float* __restrict__ in2, const float* __restrict__ W,
    const float* __restrict__ bias,
    const float* __restrict__ Wf, const float* __restrict__ Wb,
    const float* __restrict__ Wdense, const float* __restrict__ opw,
    const float* __restrict__ opb, const float* __restrict__ Wfuse,
    float* __restrict__ out)
{
    const int bx = blockIdx.x;
    const int tid = threadIdx.x;
    if (bx < CVT2_BLOCKS) {
        size_t base = (size_t)bx * 16384 + tid * 8;
#pragma unroll
        for (int it = 0; it < 8; it++) {
            size_t o = base + (size_t)it * 2048;
            float4 v0 = *(const float4*)(bert + o);
            float4 v1 = *(const float4*)(bert + o + 4);
            *(uint4*)(g_bert_h + o) = cvt8bf(v0, v1);
        }
    } else if (bx < CVT2_BLOCKS + QKV2_BLOCKS) {
        __shared__ float xs[64 * 33];
        __shared__ float ws[96 * 32];
        __shared__ float bs[96];
        const int m0 = (bx - CVT2_BLOCKS) * 64;
        for (int i = tid; i < 64 * 32; i += 256) {
            int row = i >> 5, col = i & 31;
            xs[row * 33 + col] = in2[(size_t)(m0 + row) * P + col];
        }
        for (int i = tid; i < 96 * 32; i += 256) ws[i] = W[i];
        if (tid < 96) bs[tid] = bias[tid];
        __syncthreads();

        const int m = tid >> 2;
        const int ng = tid & 3;
        float x[32];
#pragma unroll
        for (int k = 0; k < 32; k++) x[k] = xs[m * 33 + k];
        float* orow = g_qkv + (size_t)(m0 + m) * (3 * P);
#pragma unroll 4
        for (int jn = 0; jn < 24; jn++) {
            int n = ng * 24 + jn;
            const float4* wv = (const float4*)(ws + n * 32);
            float acc = bs[n];
#pragma unroll
            for (int k4 = 0; k4 < 8; k4++) {
                float4 wq = wv[k4];
                acc = fmaf(x[4 * k4], wq.x, acc);
                acc = fmaf(x[4 * k4 + 1], wq.y, acc);
                acc = fmaf(x[4 * k4 + 2], wq.z, acc);
                acc = fmaf(x[4 * k4 + 3], wq.w, acc);
            }
            orow[n] = acc;
        }
    } else if (bx < CVT2_BLOCKS + QKV2_BLOCKS + WCVT2_BLOCKS) {
        const int half = G * E;
        int base = (bx - CVT2_BLOCKS - QKV2_BLOCKS) * 16384 + tid * 8;
#pragma unroll
        for (int it = 0; it < 8; it++) {
            int o = base + it * 2048;
            const float* src = (o < half) ? (Wf + o) : (Wb + o - half);
            float4 v0 = *(const float4*)(src);
            float4 v1 = *(const float4*)(src + 4);
            *(uint4*)(g_wh + o) = cvt8bf(v0, v1);
        }
    } else {
        for (int i = tid; i < 256 * 3; i += 256) g_flags[i] = 0;
        if (tid == 0) out[0] = 0.0f;
        for (int i = tid; i < 2 * H * T; i += 256) {
            int t = i >> 7, j = i & 127;
            float s = 0.f;
#pragma unroll
            for (int u = 0; u < T; u++) s = fmaf(Wdense[j * T + u], Wfuse[u * T + t], s);
            g_weff1T[t * 2 * H + j] = s;
        }
        for (int i = tid; i < P * T; i += 256) {
            int t = i >> 5, d = i & 31;
            float s = 0.f;
#pragma unroll
            for (int p = 0; p < P; p++) s = fmaf(opw[p * P + d], Wfuse[(T + p) * T + t], s);
            g_weff2T[t * P + d] = s;
        }
        if (tid < T) {
            float s = 0.f;
#pragma unroll
            for (int p = 0; p < P; p++) s = fmaf(opb[p], Wfuse[(T + p) * T + tid], s);
            g_beff[tid] = s;
        }
        __threadfence();
    }
}

// ---------------- emissions ----------------
__global__ void __launch_bounds__(256) emis_kernel() {
    __shared__ float lrow[16 * 2 * H];
    __shared__ float arow[16 * P];
    __shared__ float w1s[T * 133];
    __shared__ float w2s[T * 37];
    __shared__ float bes[T];
    const int tid = threadIdx.x;
    const int r0 = blockIdx.x * 16;

    for (int i = tid; i < 16 * 2 * H; i += 256) lrow[i] = g_lstm[(size_t)r0 * 2 * H + i];
    for (int i = tid; i < 16 * P; i += 256) arow[i] = g_av[(size_t)r0 * P + i];
    for (int i = tid; i < T * 2 * H; i += 256) {
        int t = i >> 7, j = i & 127;
        w1s[t * 133 + j] = g_weff1T[i];
    }
    for (int i = tid; i < T * P; i += 256) {
        int t = i >> 5, d = i & 31;
        w2s[t * 37 + d] = g_weff2T[i];
    }
    if (tid < T) bes[tid] = g_beff[tid];
    __syncthreads();

    const int rr = tid >> 4;
    const int t = tid & 15;
    float acc = bes[t];
    const float* lr = lrow + rr * 2 * H;
    const float* w1 = w1s + t * 133;
#pragma unroll
    for (int i = 0; i < 2 * H; i += 4) {
        acc = fmaf(lr[i], w1[i], acc);
        acc = fmaf(lr[i + 1], w1[i + 1], acc);
        acc = fmaf(lr[i + 2], w1[i + 2], acc);
        acc = fmaf(lr[i + 3], w1[i + 3], acc);
    }
    const float* ar = arow + rr * P;
    const float* w2 = w2s + t * 37;
#pragma unroll
    for (int i = 0; i < P; i += 4) {
        acc = fmaf(ar[i], w2[i], acc);
        acc = fmaf(ar[i + 1], w2[i + 1], acc);
        acc = fmaf(ar[i + 2], w2[i + 2], acc);
        acc = fmaf(ar[i + 3], w2[i + 3], acc);
    }
    g_emis[(size_t)(r0 + rr) * T + t] = acc;
}

// =================================================================
// CRF: fwd/bwd split, 3-deep emission prefetch, fused mean (atomicAdd)
// =================================================================
__global__ void __launch_bounds__(64) crf_kernel(
    const int* __restrict__ targets, const float* __restrict__ crf_start,
    const float* __restrict__ crf_end, const float* __restrict__ crf_trans,
    float* __restrict__ out)
{
    __shared__ float tr[T * 17];
    __shared__ float alpha_s[T];
    __shared__ float beta_s[T];
    __shared__ float numw[2];
    const int b = blockIdx.x;
    const int tid = threadIdx.x;
    const int wid = tid >> 5, lane = tid & 31;
    const int j = lane & 15, half = lane >> 4;

    for (int i = tid; i < T * T; i += 64) tr[(i >> 4) * 17 + (i & 15)] = crf_trans[i];
    __syncthreads();

    const int* tg = targets + (size_t)b * S;
    {
        float num = 0.f;
        for (int t = tid; t < S; t += 64) {
            int cur = tg[t];
            num += g_emis[((size_t)b * S + t) * T + cur];
            if (t < S - 1) num += tr[cur * 17 + tg[t + 1]];
        }
#pragma unroll
        for (int o = 16; o > 0; o >>= 1) num += __shfl_xor_sync(0xffffffffu, num, o);
        if (lane == 0) numw[wid] = num;
    }

    const float* em_b = g_emis + (size_t)b * S * T;
    const int src_base = half * 24;

    if (wid == 0) {
        float Ereg[8];
#pragma unroll
        for (int k = 0; k < 8; k++) Ereg[k] = __expf(tr[(half * 8 + k) * 17 + j]);
        float a = crf_start[j] + em_b[j];
        // 3-deep prefetch ring: e0 = row t, e1 = row t+1, e2 = row t+2
        float e0 = em_b[1 * T + j];
        float e1 = em_b[2 * T + j];
        float e2 = em_b[3 * T + j];
        for (int t = 1; t <= 255; t++) {
            float e3 = em_b[(t + 3) * T + j];   // reads up to row 258 (< 512, valid)
            float anchor = __shfl_sync(0xffffffffu, a, 0);
            float e = __expf(a - anchor);
            float acc0 = 0.f, acc1 = 0.f;
#pragma unroll
            for (int i = 0; i < 8; i += 2) {
                float s0 = __shfl_sync(0xffffffffu, e, src_base + i);
                float s1 = __shfl_sync(0xffffffffu, e, src_base + i + 1);
                acc0 = fmaf(s0, Ereg[i], acc0);
                acc1 = fmaf(s1, Ereg[i + 1], acc1);
            }
            float acc = acc0 + acc1;
            acc += __shfl_xor_sync(0xffffffffu, acc, 16);
            a = anchor + __logf(acc) + e0;
            e0 = e1; e1 = e2; e2 = e3;
        }
        if (half == 0) alpha_s[j] = a;
    } else {
        float EregB[8];
#pragma unroll
        for (int i2 = 0; i2 < 8; i2++) EregB[i2] = __expf(tr[j * 17 + half * 8 + i2]);
        float bt = crf_end[j];
        // backward ring: e0 = row t+1 (current em1), descending
        float e0 = em_b[511 * T + j];
        float e1 = em_b[510 * T + j];
        float e2 = em_b[509 * T + j];
        for (int t = 510; t >= 255; t--) {
            float e3 = (t >= 258) ? em_b[(t - 2) * T + j] : 0.f;  // row t-2 >= 256... prefetch row (t+1)-3
            float g = bt + e0;
            float anchor = __shfl_sync(0xffffffffu, g, 0);
            float e = __expf(g - anchor);
            float acc0 = 0.f, acc1 = 0.f;
#pragma unroll
            for (int i2 = 0; i2 < 8; i2 += 2) {
                float s0 = __shfl_sync(0xffffffffu, e, src_base + i2);
                float s1 = __shfl_sync(0xffffffffu, e, src_base + i2 + 1);
                acc0 = fmaf(s0, EregB[i2], acc0);
                acc1 = fmaf(s1, EregB[i2 + 1], acc1);
            }
            float acc = acc0 + acc1;
            acc += __shfl_xor_sync(0xffffffffu, acc, 16);
            bt = anchor + __logf(acc);
            e0 = e1; e1 = e2; e2 = e3;
        }
        if (half == 0) beta_s[j] = bt;
    }
    __syncthreads();

    if (wid == 0) {
        float v = (lane < T) ? (alpha_s[lane] + beta_s[lane]) : -1e30f;
        float m = v;
#pragma unroll
        for (int o = 16; o > 0; o >>= 1) m = fmaxf(m, __shfl_xor_sync(0xffffffffu, m, o));
        float e = (lane < T) ? __expf(v - m) : 0.f;
#pragma unroll
        for (int o = 16; o > 0; o >>= 1) e += __shfl_xor_sync(0xffffffffu, e, o);
        if (lane == 0) {
            float s_num = numw[0] + numw[1] + crf_start[tg[0]] + crf_end[tg[S - 1]];
            float nll = (m + __logf(e)) - s_num;
            atomicAdd(out, nll * (1.0f / B));
        }
    }
}

// ---------------- launch ----------------
extern "C" void kernel_launch(void* const* d_in, const int* in_sizes, int n_in,
                              void* d_out, int out_size) {
    const float* bert = (const float*)d_in[0];
    const float* input2 = (const float*)d_in[1];
    const int* targets = (const int*)d_in[2];
    const float* Wih_f = (const float*)d_in[3];
    const float* Whh_f = (const float*)d_in[4];
    const float* bih_f = (const float*)d_in[5];
    const float* bhh_f = (const float*)d_in[6];
    const float* Wih_b = (const float*)d_in[7];
    const float* Whh_b = (const float*)d_in[8];
    const float* bih_b = (const float*)d_in[9];
    const float* bhh_b = (const float*)d_in[10];
    const float* Wdense = (const float*)d_in[11];
    const float* in_proj_w = (const float*)d_in[12];
    const float* in_proj_b = (const float*)d_in[13];
    const float* out_proj_w = (const float*)d_in[14];
    const float* out_proj_b = (const float*)d_in[15];
    const float* Wfuse = (const float*)d_in[16];
    const float* crf_start = (const float*)d_in[17];
    const float* crf_end = (const float*)d_in[18];
    const float* crf_trans = (const float*)d_in[19];
    float* out = (float*)d_out;

    cudaFuncSetAttribute(mega_kernel, cudaFuncAttributeMaxDynamicSharedMemorySize, DSM_BYTES);

    // prep: conversions + qkv + weff + flag/out reset
    prep_kernel<<<CVT2_BLOCKS + QKV2_BLOCKS + WCVT2_BLOCKS + 1, 256>>>(
        bert, input2, in_proj_w, in_proj_b, Wih_f, Wih_b,
        Wdense, out_proj_w, out_proj_b, Wfuse, out);
    // GRU + GEMM + attention
    mega_kernel<<<ATTN_OFF + 512, 256, DSM_BYTES>>>(bih_f, bih_b,
                                                    Whh_f, Whh_b, bhh_f, bhh_b);
    // emissions
    emis_kernel<<<(B * S) / 16, 256>>>();
    // CRF + fused mean
    crf_kernel<<<B, 64>>>(targets, crf_start, crf_end, crf_trans, out);
}